// round 11
// baseline (speedup 1.0000x reference)
#include <cuda_runtime.h>
#include <stdint.h>

#define GH 52
#define GW 52
#define NB 5
#define NBOX 13520                 // 52*52*5
#define ROWBITS 288                // padded positions per grid row (260 used)
#define PWORDS 468
#define PPOS   (PWORDS*32)         // 14976 padded positions
#define IOU_T  0.4f
#define STK    80
#define RES_T  1024

// Per-position predecessor masks (padded layout): x=dy-1, y=dy0, z=dy+1,
// 15 bits each (bit (dx+1)*5+bb). w is NEVER written -> stays 0 forever, so
// a raw 64-bit load yields exactly the 48-bit mask. Padding positions are
// never written and stay zero.
__device__ ushort4 g_pm[PPOS];

// ---------------------------------------------------------------------------
// Kernel 1: decode + predecessor masks (proven-exact branchless version).
// One thread per (box, dyRow).
// ---------------------------------------------------------------------------
__global__ void decode_kernel(const float* __restrict__ x, float* __restrict__ out)
{
    int id = blockIdx.x * blockDim.x + threadIdx.x;
    if (id >= 3 * NBOX) return;
    int dyI = id / NBOX;            // 0,1,2 -> dy = dyI-1
    int j   = id - dyI * NBOX;

    int cell = j / NB;
    int b    = j - cell * NB;
    int gy   = cell / GW;
    int gx   = cell - gy * GW;

    const float sx = 416.0f / GW;   // 8
    const float sy = 416.0f / GH;   // 8

    const float* p = x + j * 5;
    float c0 = p[0], c1 = p[1], c2 = p[2], c3 = p[3], sj = p[4];

    float cx = (c0 + (float)gx) * sx;
    float w  = c2 * sx;
    float cy = (c1 + (float)gy) * sy;
    float h  = c3 * sy;
    cy = 416.0f - cy;
    float jx1 = cx - w * 0.5f, jy1 = cy - h * 0.5f;
    float jx2 = cx + w * 0.5f, jy2 = cy + h * 0.5f;

    if (dyI == 1) {
        float* o = out + j * 5;
        o[0] = jx1; o[1] = jy1; o[2] = jx2; o[3] = jy2;
        // o[4] written by resolve_kernel.
    }

    float aj = fmaxf(jx2 - jx1, 0.0f) * fmaxf(jy2 - jy1, 0.0f);

    unsigned mask = 0;
    int ny = gy + dyI - 1;
    if ((unsigned)ny < GH) {
        #pragma unroll
        for (int dxi = 0; dxi < 3; dxi++) {
            int nx = gx + dxi - 1;
            if ((unsigned)nx >= GW) continue;
            int ncell = ny * GW + nx;
            const float* cp = x + ncell * 25;
            float q[25];
            #pragma unroll
            for (int k = 0; k < 25; k++) q[k] = cp[k];

            #pragma unroll
            for (int bb = 0; bb < NB; bb++) {
                int i = ncell * NB + bb;
                float si = q[bb * 5 + 4];
                bool higher = (si > sj) || (si == sj && i < j);
                float d0 = q[bb * 5 + 0], d1 = q[bb * 5 + 1];
                float d2 = q[bb * 5 + 2], d3 = q[bb * 5 + 3];
                float icx = (d0 + (float)nx) * sx;
                float iw_ = d2 * sx;
                float icy = (d1 + (float)ny) * sy;
                float ih_ = d3 * sy;
                icy = 416.0f - icy;
                float ix1 = icx - iw_ * 0.5f, iy1 = icy - ih_ * 0.5f;
                float ix2 = icx + iw_ * 0.5f, iy2 = icy + ih_ * 0.5f;

                float iw = fmaxf(fminf(ix2, jx2) - fmaxf(ix1, jx1), 0.0f);
                float ih = fmaxf(fminf(iy2, jy2) - fmaxf(iy1, jy1), 0.0f);
                float inter = iw * ih;
                float ai  = fmaxf(ix2 - ix1, 0.0f) * fmaxf(iy2 - iy1, 0.0f);
                float uni = ai + aj - inter;
                float iou = (uni > 0.0f) ? inter / fmaxf(uni, 1e-12f) : 0.0f;
                bool on = (iou > IOU_T) && higher && (i != j);
                mask |= (on ? 1u : 0u) << (dxi * 5 + bb);
            }
        }
    }
    int pos = gy * ROWBITS + gx * 5 + b;
    ((unsigned short*)&g_pm[pos])[dyI] = (unsigned short)mask;
}

// ---------------------------------------------------------------------------
// Kernel 2: single-CTA memoized DFS with ALL state in shared memory.
// Masks staged L2->smem once; memo bytes in smem (zero-init per launch).
// Per chain link: 2 LDS (~60 cyc) instead of 2 L2 round trips (~600 cyc).
// kept[p] = no pred (higher priority, IoU>0.4) that is kept. Well-founded
// recursion -> DFS terminates; unique fixpoint == exact greedy NMS. Memo
// writes are idempotent deterministic values.
// mask bit layout: bit (dyI*16 + q), q = dxi*5+bb;
// pred = pbase + (k>>4)*ROWBITS + (k&15), pbase = pos - bb - ROWBITS - 5.
// ---------------------------------------------------------------------------
extern __shared__ uint8_t smraw[];

__global__ void __launch_bounds__(RES_T, 1)
resolve_kernel(const float* __restrict__ x, float* __restrict__ out)
{
    uint64_t*         msk = (uint64_t*)smraw;                // PPOS*8 = 117KB
    volatile uint8_t* st  = (volatile uint8_t*)(smraw + PPOS * 8);  // PPOS

    int t = threadIdx.x;

    // Stage masks (L2-resident, written by decode) + zero memo.
    const uint64_t* gm = (const uint64_t*)g_pm;
    for (int i = t; i < PPOS; i += RES_T) {
        msk[i] = __ldg(&gm[i]);     // w never written -> top 16 bits are 0
        st[i]  = 0;
    }
    __syncthreads();

    for (int j = t; j < NBOX; j += RES_T) {
        int row = j / 260;
        int rem = j - row * 260;
        int pos = row * ROWBITS + rem;

        uint64_t m0 = msk[pos];
        int res;
        if (m0 == 0ull) {
            res = 1;
            st[pos] = 1;
        } else {
            int pre = st[pos];
            if (pre) {
                res = pre;
            } else {
                int      fpos[STK], fpb[STK];
                uint64_t frem[STK];
                fpos[0] = pos;
                fpb[0]  = pos - (rem % 5) - ROWBITS - 5;
                frem[0] = m0;
                int sp = 1;
                res = 0;
                while (sp > 0) {
                    uint64_t r = frem[sp - 1];
                    int fin = 0;
                    if (r == 0ull) {
                        fin = 1;                           // no kept pred -> kept
                    } else {
                        int k = __ffsll((long long)r) - 1;
                        frem[sp - 1] = r & (r - 1);
                        int q    = k & 15;
                        int pred = fpb[sp - 1] + (k >> 4) * ROWBITS + q;
                        int sv = st[pred];
                        if (sv == 1) {
                            fin = 2;                       // kept pred -> suppressed
                        } else if (sv == 0) {
                            uint64_t m = msk[pred];
                            if (m == 0ull) {
                                st[pred] = 1;
                                fin = 2;
                            } else if (sp < STK) {
                                int bb = q - (q >= 5 ? 5 : 0);
                                bb -= (bb >= 5 ? 5 : 0);
                                fpos[sp] = pred;
                                fpb[sp]  = pred - bb - ROWBITS - 5;
                                frem[sp] = m;
                                sp++;
                            } else {
                                // Overflow fallback: some thread in this block
                                // resolves pred (well-founded order; ITS
                                // guarantees progress). Near-unreachable at
                                // STK=80.
                                int v;
                                do { v = st[pred]; } while (v == 0);
                                if (v == 1) fin = 2;
                            }
                        }
                        // sv == 2: suppressed pred, keep scanning
                    }
                    if (fin) {
                        st[fpos[sp - 1]] = (uint8_t)fin;
                        sp--;
                        if (sp == 0) {
                            res = fin;
                        } else if (fin == 1) {             // kept child -> parent supp
                            st[fpos[sp - 1]] = 2;
                            sp--;
                            if (sp == 0) res = 2;
                        }
                    }
                }
            }
        }

        out[j * 5 + 4] = (res == 1) ? __ldg(&x[j * 5 + 4]) : 0.0f;
    }
}

// ---------------------------------------------------------------------------
extern "C" void kernel_launch(void* const* d_in, const int* in_sizes, int n_in,
                              void* d_out, int out_size)
{
    const float* x   = (const float*)d_in[0];
    float*       out = (float*)d_out;

    const int smb = PPOS * 9;        // masks (8B) + memo (1B) per position
    cudaFuncSetAttribute(resolve_kernel,
                         cudaFuncAttributeMaxDynamicSharedMemorySize, smb);

    decode_kernel<<<(3 * NBOX + 255) / 256, 256>>>(x, out);
    resolve_kernel<<<1, RES_T, smb>>>(x, out);
}

// round 12
// speedup vs baseline: 1.9825x; 1.9825x over previous
#include <cuda_runtime.h>
#include <stdint.h>

#define GH 52
#define GW 52
#define NB 5
#define NBOX 13520                 // 52*52*5
#define ROWBITS 288                // padded positions per grid row (260 used)
#define PWORDS 468
#define PPOS   (PWORDS*32)         // 14976 padded positions
#define IOU_T  0.4f
#define STK    80
#define M48    0x0000FFFFFFFFFFFFull

// Per-position record (padded layout), one 64-bit word:
//   bits [0:16)  pred mask row dy=-1 (15 bits, bit (dx+1)*5+bb)
//   bits[16:32)  pred mask row dy= 0
//   bits[32:48)  pred mask row dy=+1
//   bits[48:64)  memo state: 0=unknown, 1=kept, 2=suppressed
// Decode writes the three mask rows (one per dyI thread) and resets state.
// Padding positions are never written and stay zero.
__device__ ushort4 g_pm[PPOS];

// ---------------------------------------------------------------------------
// Kernel 1: decode + predecessor masks (proven-exact branchless version)
// + memo reset. One thread per (box, dyRow).
// ---------------------------------------------------------------------------
__global__ void decode_kernel(const float* __restrict__ x, float* __restrict__ out)
{
    int id = blockIdx.x * blockDim.x + threadIdx.x;
    if (id >= 3 * NBOX) return;
    int dyI = id / NBOX;            // 0,1,2 -> dy = dyI-1
    int j   = id - dyI * NBOX;

    int cell = j / NB;
    int b    = j - cell * NB;
    int gy   = cell / GW;
    int gx   = cell - gy * GW;

    const float sx = 416.0f / GW;   // 8
    const float sy = 416.0f / GH;   // 8

    const float* p = x + j * 5;
    float c0 = p[0], c1 = p[1], c2 = p[2], c3 = p[3], sj = p[4];

    float cx = (c0 + (float)gx) * sx;
    float w  = c2 * sx;
    float cy = (c1 + (float)gy) * sy;
    float h  = c3 * sy;
    cy = 416.0f - cy;
    float jx1 = cx - w * 0.5f, jy1 = cy - h * 0.5f;
    float jx2 = cx + w * 0.5f, jy2 = cy + h * 0.5f;

    int pos = gy * ROWBITS + gx * 5 + b;

    if (dyI == 1) {
        float* o = out + j * 5;
        o[0] = jx1; o[1] = jy1; o[2] = jx2; o[3] = jy2;
        ((unsigned short*)&g_pm[pos])[3] = 0;   // memo reset (replay-safe)
        // o[4] written by resolve_kernel.
    }

    float aj = fmaxf(jx2 - jx1, 0.0f) * fmaxf(jy2 - jy1, 0.0f);

    unsigned mask = 0;
    int ny = gy + dyI - 1;
    if ((unsigned)ny < GH) {
        #pragma unroll
        for (int dxi = 0; dxi < 3; dxi++) {
            int nx = gx + dxi - 1;
            if ((unsigned)nx >= GW) continue;
            int ncell = ny * GW + nx;
            const float* cp = x + ncell * 25;
            float q[25];
            #pragma unroll
            for (int k = 0; k < 25; k++) q[k] = cp[k];

            #pragma unroll
            for (int bb = 0; bb < NB; bb++) {
                int i = ncell * NB + bb;
                float si = q[bb * 5 + 4];
                bool higher = (si > sj) || (si == sj && i < j);
                float d0 = q[bb * 5 + 0], d1 = q[bb * 5 + 1];
                float d2 = q[bb * 5 + 2], d3 = q[bb * 5 + 3];
                float icx = (d0 + (float)nx) * sx;
                float iw_ = d2 * sx;
                float icy = (d1 + (float)ny) * sy;
                float ih_ = d3 * sy;
                icy = 416.0f - icy;
                float ix1 = icx - iw_ * 0.5f, iy1 = icy - ih_ * 0.5f;
                float ix2 = icx + iw_ * 0.5f, iy2 = icy + ih_ * 0.5f;

                float iw = fmaxf(fminf(ix2, jx2) - fmaxf(ix1, jx1), 0.0f);
                float ih = fmaxf(fminf(iy2, jy2) - fmaxf(iy1, jy1), 0.0f);
                float inter = iw * ih;
                float ai  = fmaxf(ix2 - ix1, 0.0f) * fmaxf(iy2 - iy1, 0.0f);
                float uni = ai + aj - inter;
                float iou = (uni > 0.0f) ? inter / fmaxf(uni, 1e-12f) : 0.0f;
                bool on = (iou > IOU_T) && higher && (i != j);
                mask |= (on ? 1u : 0u) << (dxi * 5 + bb);
            }
        }
    }
    ((unsigned short*)&g_pm[pos])[dyI] = (unsigned short)mask;
}

// ---------------------------------------------------------------------------
// Kernel 2: per-box memoized DFS, one thread per box, no barriers.
// Each node = ONE plain (L1-cacheable) 64-bit load of mask+state.
// Correctness under stale L1 reads: state is monotone 0 -> {1,2} with a
// deterministic final value; a stale 0 only causes recomputation of the
// same deterministic result. Well-founded recursion (priority strictly
// increases along preds) => termination; unique fixpoint == exact greedy
// NMS. The overflow spin uses a volatile read so it cannot livelock.
// Node addressing: bit k -> pred = pbase + (k>>4)*ROWBITS + (k&15),
// pbase = pos - bb - ROWBITS - 5.
// ---------------------------------------------------------------------------
__device__ __forceinline__ void set_state(int pos, unsigned short v)
{
    ((unsigned short*)&g_pm[pos])[3] = v;
}

__global__ void __launch_bounds__(256)
resolve_kernel(const float* __restrict__ x, float* __restrict__ out)
{
    int j = blockIdx.x * blockDim.x + threadIdx.x;
    if (j >= NBOX) return;
    int row = j / 260;
    int rem = j - row * 260;
    int pos = row * ROWBITS + rem;

    const uint64_t* gm = (const uint64_t*)g_pm;

    uint64_t w0 = gm[pos];
    int res = (int)(w0 >> 48);
    if (res == 0) {
        if ((w0 & M48) == 0ull) {
            res = 1;
            set_state(pos, 1);
        } else {
            int      fpos[STK], fpb[STK];
            uint64_t frem[STK];
            fpos[0] = pos;
            fpb[0]  = pos - (rem % 5) - ROWBITS - 5;
            frem[0] = w0 & M48;
            int sp = 1;
            while (sp > 0) {
                uint64_t r = frem[sp - 1];
                int fin = 0;
                if (r == 0ull) {
                    fin = 1;                           // no kept pred -> kept
                } else {
                    int k = __ffsll((long long)r) - 1;
                    frem[sp - 1] = r & (r - 1);
                    int q    = k & 15;
                    int pred = fpb[sp - 1] + (k >> 4) * ROWBITS + q;
                    uint64_t wp = gm[pred];            // ONE load: mask+state
                    int sv = (int)(wp >> 48);
                    if (sv == 1) {
                        fin = 2;                       // kept pred -> suppressed
                    } else if (sv == 0) {
                        uint64_t m = wp & M48;
                        if (m == 0ull) {
                            set_state(pred, 1);
                            fin = 2;
                        } else if (sp < STK) {
                            int bb = q - (q >= 5 ? 5 : 0);
                            bb -= (bb >= 5 ? 5 : 0);
                            fpos[sp] = pred;
                            fpb[sp]  = pred - bb - ROWBITS - 5;
                            frem[sp] = m;
                            sp++;
                        } else {
                            // Overflow fallback: pred's own thread decides it
                            // (well-founded order => terminates). Volatile so
                            // the spin observes the update.
                            volatile unsigned short* vs =
                                &((unsigned short*)&g_pm[pred])[3];
                            unsigned short v;
                            do { v = *vs; } while (v == 0);
                            if (v == 1) fin = 2;
                        }
                    }
                    // sv == 2: suppressed pred, keep scanning
                }
                if (fin) {
                    set_state(fpos[sp - 1], (unsigned short)fin);
                    sp--;
                    if (sp == 0) {
                        res = fin;
                    } else if (fin == 1) {             // kept child -> parent supp
                        set_state(fpos[sp - 1], 2);
                        sp--;
                        if (sp == 0) res = 2;
                    }
                }
            }
        }
    }

    out[j * 5 + 4] = (res == 1) ? __ldg(&x[j * 5 + 4]) : 0.0f;
}

// ---------------------------------------------------------------------------
extern "C" void kernel_launch(void* const* d_in, const int* in_sizes, int n_in,
                              void* d_out, int out_size)
{
    const float* x   = (const float*)d_in[0];
    float*       out = (float*)d_out;

    decode_kernel<<<(3 * NBOX + 255) / 256, 256>>>(x, out);
    resolve_kernel<<<(NBOX + 255) / 256, 256>>>(x, out);
}